// round 4
// baseline (speedup 1.0000x reference)
#include <cuda_runtime.h>
#include <math.h>

// ---------------------------------------------------------------------------
// SpatialTransformer (SD-style), fp32 SIMT, round-2 GEMM upgrade.
// x [1,320,64,64] -> GN(32) -> 1x1 conv -> [4096,320] tokens
// -> LN+selfattn+res -> LN+crossattn(77x768)+res -> LN+GEGLU FF+res
// -> 1x1 conv -> + x
// ---------------------------------------------------------------------------

#define HW    4096
#define CCH   320
#define GROUPS 32
#define CPG   10
#define HEADS 8
#define DH    40
#define CTXN  77
#define CTXD  768
#define FFI   1280

// Scratch (device globals: no allocation allowed)
__device__ float g_mu[GROUPS], g_rs[GROUPS];
__device__ float g_gnA[HW * CCH];
__device__ float g_res[HW * CCH];
__device__ float g_ln[HW * CCH];
__device__ float g_q[HW * CCH];
__device__ float g_k[HW * CCH];
__device__ float g_v[HW * CCH];
__device__ float g_attn[HW * CCH];
__device__ float g_ffh[HW * 2 * FFI];
__device__ float g_gg[HW * FFI];
__device__ float g_kc[CTXN * CCH];
__device__ float g_vc[CTXN * CCH];

// ---------------------------------------------------------------------------
// GroupNorm stats: one block per group
// ---------------------------------------------------------------------------
__global__ void gn_stats_kernel(const float* __restrict__ x) {
    int g = blockIdx.x;
    int tid = threadIdx.x;                 // 256
    const float* xg = x + (size_t)g * CPG * HW;
    float s = 0.f, s2 = 0.f;
    for (int i = tid; i < CPG * HW; i += 256) {
        float v = xg[i];
        s += v; s2 += v * v;
    }
    __shared__ float r1[8], r2[8];
    int lane = tid & 31, wp = tid >> 5;
    #pragma unroll
    for (int o = 16; o; o >>= 1) {
        s  += __shfl_xor_sync(0xffffffffu, s,  o);
        s2 += __shfl_xor_sync(0xffffffffu, s2, o);
    }
    if (lane == 0) { r1[wp] = s; r2[wp] = s2; }
    __syncthreads();
    if (tid == 0) {
        float t = 0.f, t2 = 0.f;
        for (int i = 0; i < 8; i++) { t += r1[i]; t2 += r2[i]; }
        float inv = 1.f / (float)(CPG * HW);
        float mean = t * inv;
        float var  = t2 * inv - mean * mean;
        g_mu[g] = mean;
        g_rs[g] = rsqrtf(var + 1e-6f);
    }
}

// ---------------------------------------------------------------------------
// GroupNorm apply + transpose: x [C, HW] -> out [HW, C] normalized
// ---------------------------------------------------------------------------
__global__ void gn_apply_kernel(const float* __restrict__ x, const float* __restrict__ w,
                                const float* __restrict__ b, float* __restrict__ o) {
    __shared__ float tile[32][33];
    int n0 = blockIdx.x * 32, c0 = blockIdx.y * 32;
    int tx = threadIdx.x, ty = threadIdx.y;  // 32 x 8
    for (int r = ty; r < 32; r += 8)
        tile[r][tx] = x[(size_t)(c0 + r) * HW + n0 + tx];
    __syncthreads();
    for (int r = ty; r < 32; r += 8) {
        int c = c0 + tx, n = n0 + r;
        int g = c / CPG;
        o[(size_t)n * CCH + c] = (tile[tx][r] - g_mu[g]) * g_rs[g] * w[c] + b[c];
    }
}

// ---------------------------------------------------------------------------
// Tiled SGEMM: C[M,N] = A[M,K] * B (+ bias) (+ resid)
//   TB=false: B is [K,N] row-major.  TB=true: B is [N,K] row-major (B^T).
//   BIAS_ROW=false: bias[n] per column. BIAS_ROW=true: bias[m] per row.
// 128x128 tile, BK=8, 256 threads, 8x8 micro-tile, float4 global loads.
// Requires K % 8 == 0.
// ---------------------------------------------------------------------------
template <bool TB, bool BIAS_ROW>
__global__ __launch_bounds__(256) void sgemm_kernel(
        const float* __restrict__ A, const float* __restrict__ B,
        const float* __restrict__ bias, const float* __restrict__ resid,
        float* __restrict__ C, int M, int N, int K) {
    __shared__ float As[8][128];
    __shared__ float Bs[8][128];
    const int bm = blockIdx.y * 128, bn = blockIdx.x * 128;
    const int tid = threadIdx.x;           // 256
    const int tx = tid & 15, ty = tid >> 4;

    // A loader: row = tid>>1 (0..127), k-quad = (tid&1)*4
    const int arow = tid >> 1;
    const int akq  = (tid & 1) * 4;
    // B loader (TB=false): k = tid>>5 (0..7), n-quad = (tid&31)*4
    const int bkr  = tid >> 5;
    const int bnq  = (tid & 31) * 4;
    // B loader (TB=true): n = tid>>1, k-quad = (tid&1)*4
    const int bnr  = tid >> 1;
    const int bkq  = (tid & 1) * 4;

    float acc[8][8];
    #pragma unroll
    for (int i = 0; i < 8; i++)
        #pragma unroll
        for (int j = 0; j < 8; j++) acc[i][j] = 0.f;

    for (int k0 = 0; k0 < K; k0 += 8) {
        // load A tile (transposed into As[k][m])
        {
            int gm = bm + arow;
            float4 v = make_float4(0.f, 0.f, 0.f, 0.f);
            if (gm < M) v = *(const float4*)(A + (size_t)gm * K + k0 + akq);
            As[akq + 0][arow] = v.x;
            As[akq + 1][arow] = v.y;
            As[akq + 2][arow] = v.z;
            As[akq + 3][arow] = v.w;
        }
        // load B tile into Bs[k][n]
        if (!TB) {
            int gn = bn + bnq;
            float4 v;
            if (gn + 3 < N) {
                v = *(const float4*)(B + (size_t)(k0 + bkr) * N + gn);
            } else {
                v.x = (gn + 0 < N) ? B[(size_t)(k0 + bkr) * N + gn + 0] : 0.f;
                v.y = (gn + 1 < N) ? B[(size_t)(k0 + bkr) * N + gn + 1] : 0.f;
                v.z = (gn + 2 < N) ? B[(size_t)(k0 + bkr) * N + gn + 2] : 0.f;
                v.w = 0.f;
            }
            *(float4*)&Bs[bkr][bnq] = v;
        } else {
            int gn = bn + bnr;
            float4 v = make_float4(0.f, 0.f, 0.f, 0.f);
            if (gn < N) v = *(const float4*)(B + (size_t)gn * K + k0 + bkq);
            Bs[bkq + 0][bnr] = v.x;
            Bs[bkq + 1][bnr] = v.y;
            Bs[bkq + 2][bnr] = v.z;
            Bs[bkq + 3][bnr] = v.w;
        }
        __syncthreads();

        #pragma unroll
        for (int k = 0; k < 8; k++) {
            float a[8], bb[8];
            *(float4*)&a[0]  = *(const float4*)&As[k][ty * 8];
            *(float4*)&a[4]  = *(const float4*)&As[k][ty * 8 + 4];
            *(float4*)&bb[0] = *(const float4*)&Bs[k][tx * 8];
            *(float4*)&bb[4] = *(const float4*)&Bs[k][tx * 8 + 4];
            #pragma unroll
            for (int i = 0; i < 8; i++)
                #pragma unroll
                for (int j = 0; j < 8; j++) acc[i][j] += a[i] * bb[j];
        }
        __syncthreads();
    }

    #pragma unroll
    for (int i = 0; i < 8; i++) {
        int gm = bm + ty * 8 + i;
        if (gm >= M) continue;
        #pragma unroll
        for (int j = 0; j < 8; j++) {
            int gn = bn + tx * 8 + j;
            if (gn >= N) continue;
            float v = acc[i][j];
            if (bias)  v += BIAS_ROW ? bias[gm] : bias[gn];
            if (resid) v += resid[(size_t)gm * N + gn];
            C[(size_t)gm * N + gn] = v;
        }
    }
}

// ---------------------------------------------------------------------------
// LayerNorm over last dim 320, one block (320 threads) per row
// ---------------------------------------------------------------------------
__global__ void ln_kernel(const float* __restrict__ x, const float* __restrict__ w,
                          const float* __restrict__ b, float* __restrict__ y) {
    int row = blockIdx.x;
    int tid = threadIdx.x;                 // 320
    float v = x[(size_t)row * CCH + tid];
    __shared__ float red[10];
    __shared__ float s_mean, s_rstd;
    int lane = tid & 31, wp = tid >> 5;
    float s = v;
    #pragma unroll
    for (int o = 16; o; o >>= 1) s += __shfl_xor_sync(0xffffffffu, s, o);
    if (lane == 0) red[wp] = s;
    __syncthreads();
    if (tid == 0) {
        float t = 0.f;
        for (int i = 0; i < 10; i++) t += red[i];
        s_mean = t / (float)CCH;
    }
    __syncthreads();
    float d = v - s_mean;
    s = d * d;
    #pragma unroll
    for (int o = 16; o; o >>= 1) s += __shfl_xor_sync(0xffffffffu, s, o);
    if (lane == 0) red[wp] = s;
    __syncthreads();
    if (tid == 0) {
        float t = 0.f;
        for (int i = 0; i < 10; i++) t += red[i];
        s_rstd = rsqrtf(t / (float)CCH + 1e-5f);
    }
    __syncthreads();
    y[(size_t)row * CCH + tid] = d * s_rstd * w[tid] + b[tid];
}

// ---------------------------------------------------------------------------
// Fused flash-style attention.
// Q [Nq=4096, 320], K/V [Mk, 320]. Per-block: 64 queries x one head.
// ---------------------------------------------------------------------------
#define QB 64
#define TK 64

__global__ __launch_bounds__(256) void attn_kernel(
    const float* __restrict__ Q, const float* __restrict__ K,
    const float* __restrict__ V, float* __restrict__ O, int Mk) {
    __shared__ float Qt[QB][DH + 1];
    __shared__ float Kt[TK][DH + 1];
    __shared__ float Vt[TK][DH + 1];
    __shared__ float P[QB][TK + 1];
    __shared__ float s_m[QB], s_l[QB], s_al[QB];

    const int h   = blockIdx.y;
    const int q0  = blockIdx.x * QB;
    const int tid = threadIdx.x;           // 256
    const float scale = 0.15811388300841898f;  // 40^-0.5
    const int off = h * DH;

    for (int i = tid; i < QB * DH; i += 256) {
        int r = i / DH, c = i % DH;
        Qt[r][c] = Q[(size_t)(q0 + r) * CCH + off + c];
    }
    if (tid < QB) { s_m[tid] = -INFINITY; s_l[tid] = 0.f; }

    float acc[2][5];
    #pragma unroll
    for (int i = 0; i < 2; i++)
        #pragma unroll
        for (int j = 0; j < 5; j++) acc[i][j] = 0.f;
    const int aq = (tid >> 3) * 2;
    const int ad = (tid & 7) * 5;
    const int sq = (tid >> 4) * 4;
    const int sk = (tid & 15) * 4;

    __syncthreads();

    for (int kb = 0; kb < Mk; kb += TK) {
        int nk = min(TK, Mk - kb);
        for (int i = tid; i < TK * DH; i += 256) {
            int r = i / DH, c = i % DH;
            float kv = 0.f, vv = 0.f;
            if (r < nk) {
                kv = K[(size_t)(kb + r) * CCH + off + c];
                vv = V[(size_t)(kb + r) * CCH + off + c];
            }
            Kt[r][c] = kv;
            Vt[r][c] = vv;
        }
        __syncthreads();

        float s[4][4];
        #pragma unroll
        for (int i = 0; i < 4; i++)
            #pragma unroll
            for (int j = 0; j < 4; j++) s[i][j] = 0.f;
        #pragma unroll
        for (int c = 0; c < DH; c++) {
            float qv[4], kv[4];
            #pragma unroll
            for (int i = 0; i < 4; i++) qv[i] = Qt[sq + i][c];
            #pragma unroll
            for (int j = 0; j < 4; j++) kv[j] = Kt[sk + j][c];
            #pragma unroll
            for (int i = 0; i < 4; i++)
                #pragma unroll
                for (int j = 0; j < 4; j++) s[i][j] += qv[i] * kv[j];
        }
        #pragma unroll
        for (int i = 0; i < 4; i++)
            #pragma unroll
            for (int j = 0; j < 4; j++)
                P[sq + i][sk + j] = (sk + j < nk) ? s[i][j] * scale : -INFINITY;
        __syncthreads();

        {
            int w = tid >> 5, lane = tid & 31;
            for (int r = w * 8; r < w * 8 + 8; r++) {
                float s0 = P[r][lane], s1 = P[r][lane + 32];
                float mx = fmaxf(s0, s1);
                #pragma unroll
                for (int o = 16; o; o >>= 1) mx = fmaxf(mx, __shfl_xor_sync(0xffffffffu, mx, o));
                float mold = s_m[r];
                float mnew = fmaxf(mold, mx);
                float p0 = __expf(s0 - mnew), p1 = __expf(s1 - mnew);
                P[r][lane] = p0; P[r][lane + 32] = p1;
                float sum = p0 + p1;
                #pragma unroll
                for (int o = 16; o; o >>= 1) sum += __shfl_xor_sync(0xffffffffu, sum, o);
                if (lane == 0) {
                    float al = __expf(mold - mnew);
                    s_l[r] = s_l[r] * al + sum;
                    s_m[r] = mnew;
                    s_al[r] = al;
                }
            }
        }
        __syncthreads();

        float al0 = s_al[aq], al1 = s_al[aq + 1];
        #pragma unroll
        for (int j = 0; j < 5; j++) { acc[0][j] *= al0; acc[1][j] *= al1; }
        for (int k = 0; k < nk; k++) {
            float p0 = P[aq][k], p1 = P[aq + 1][k];
            #pragma unroll
            for (int j = 0; j < 5; j++) {
                float vv = Vt[k][ad + j];
                acc[0][j] += p0 * vv;
                acc[1][j] += p1 * vv;
            }
        }
        __syncthreads();
    }

    float inv0 = 1.f / s_l[aq], inv1 = 1.f / s_l[aq + 1];
    #pragma unroll
    for (int j = 0; j < 5; j++) {
        O[(size_t)(q0 + aq)     * CCH + off + ad + j] = acc[0][j] * inv0;
        O[(size_t)(q0 + aq + 1) * CCH + off + ad + j] = acc[1][j] * inv1;
    }
}

// ---------------------------------------------------------------------------
// GEGLU: out[n,j] = a[n,j] * gelu_exact(g[n,j])
// ---------------------------------------------------------------------------
__global__ void geglu_kernel(const float* __restrict__ h, float* __restrict__ o) {
    int idx = blockIdx.x * blockDim.x + threadIdx.x;
    if (idx >= HW * FFI) return;
    int n = idx / FFI, j = idx % FFI;
    float a = h[(size_t)n * 2 * FFI + j];
    float g = h[(size_t)n * 2 * FFI + FFI + j];
    float ge = 0.5f * g * (1.f + erff(g * 0.70710678118654752f));
    o[idx] = a * ge;
}

// ---------------------------------------------------------------------------
// Host launcher
// ---------------------------------------------------------------------------
static inline dim3 gemm_grid(int M, int N) {
    return dim3((N + 127) / 128, (M + 127) / 128);
}

extern "C" void kernel_launch(void* const* d_in, const int* in_sizes, int n_in,
                              void* d_out, int out_size) {
    const float* x       = (const float*)d_in[0];
    const float* context = (const float*)d_in[1];
    const float* gn_w    = (const float*)d_in[2];
    const float* gn_b    = (const float*)d_in[3];
    const float* pin_w   = (const float*)d_in[4];
    const float* pin_b   = (const float*)d_in[5];
    const float* ln1_w   = (const float*)d_in[6];
    const float* ln1_b   = (const float*)d_in[7];
    const float* q1      = (const float*)d_in[8];
    const float* k1      = (const float*)d_in[9];
    const float* v1      = (const float*)d_in[10];
    const float* o1_w    = (const float*)d_in[11];
    const float* o1_b    = (const float*)d_in[12];
    const float* ln2_w   = (const float*)d_in[13];
    const float* ln2_b   = (const float*)d_in[14];
    const float* q2      = (const float*)d_in[15];
    const float* k2      = (const float*)d_in[16];
    const float* v2      = (const float*)d_in[17];
    const float* o2_w    = (const float*)d_in[18];
    const float* o2_b    = (const float*)d_in[19];
    const float* ln3_w   = (const float*)d_in[20];
    const float* ln3_b   = (const float*)d_in[21];
    const float* ff1_w   = (const float*)d_in[22];
    const float* ff1_b   = (const float*)d_in[23];
    const float* ff2_w   = (const float*)d_in[24];
    const float* ff2_b   = (const float*)d_in[25];
    const float* pout_w  = (const float*)d_in[26];
    const float* pout_b  = (const float*)d_in[27];
    float* out = (float*)d_out;

    float *gnA, *res, *ln, *q, *k, *v, *attn, *ffh, *gg, *kc, *vc;
    cudaGetSymbolAddress((void**)&gnA,  g_gnA);
    cudaGetSymbolAddress((void**)&res,  g_res);
    cudaGetSymbolAddress((void**)&ln,   g_ln);
    cudaGetSymbolAddress((void**)&q,    g_q);
    cudaGetSymbolAddress((void**)&k,    g_k);
    cudaGetSymbolAddress((void**)&v,    g_v);
    cudaGetSymbolAddress((void**)&attn, g_attn);
    cudaGetSymbolAddress((void**)&ffh,  g_ffh);
    cudaGetSymbolAddress((void**)&gg,   g_gg);
    cudaGetSymbolAddress((void**)&kc,   g_kc);
    cudaGetSymbolAddress((void**)&vc,   g_vc);

    // 1. GroupNorm + transpose to [HW, C]
    gn_stats_kernel<<<GROUPS, 256>>>(x);
    gn_apply_kernel<<<dim3(HW / 32, CCH / 32), dim3(32, 8)>>>(x, gn_w, gn_b, gnA);

    // 2. proj_in (conv1x1): h0 = gnA @ pin_w^T + pin_b  -> res
    sgemm_kernel<true, false><<<gemm_grid(HW, CCH), 256>>>(gnA, pin_w, pin_b, nullptr, res, HW, CCH, CCH);

    // 3. self-attention block
    ln_kernel<<<HW, CCH>>>(res, ln1_w, ln1_b, ln);
    sgemm_kernel<false, false><<<gemm_grid(HW, CCH), 256>>>(ln, q1, nullptr, nullptr, q, HW, CCH, CCH);
    sgemm_kernel<false, false><<<gemm_grid(HW, CCH), 256>>>(ln, k1, nullptr, nullptr, k, HW, CCH, CCH);
    sgemm_kernel<false, false><<<gemm_grid(HW, CCH), 256>>>(ln, v1, nullptr, nullptr, v, HW, CCH, CCH);
    attn_kernel<<<dim3(HW / QB, HEADS), 256>>>(q, k, v, attn, HW);
    sgemm_kernel<false, false><<<gemm_grid(HW, CCH), 256>>>(attn, o1_w, o1_b, res, res, HW, CCH, CCH);

    // 4. cross-attention block
    ln_kernel<<<HW, CCH>>>(res, ln2_w, ln2_b, ln);
    sgemm_kernel<false, false><<<gemm_grid(HW, CCH), 256>>>(ln, q2, nullptr, nullptr, q, HW, CCH, CCH);
    sgemm_kernel<false, false><<<gemm_grid(CTXN, CCH), 256>>>(context, k2, nullptr, nullptr, kc, CTXN, CCH, CTXD);
    sgemm_kernel<false, false><<<gemm_grid(CTXN, CCH), 256>>>(context, v2, nullptr, nullptr, vc, CTXN, CCH, CTXD);
    attn_kernel<<<dim3(HW / QB, HEADS), 256>>>(q, kc, vc, attn, CTXN);
    sgemm_kernel<false, false><<<gemm_grid(HW, CCH), 256>>>(attn, o2_w, o2_b, res, res, HW, CCH, CCH);

    // 5. GEGLU feed-forward
    ln_kernel<<<HW, CCH>>>(res, ln3_w, ln3_b, ln);
    sgemm_kernel<false, false><<<gemm_grid(HW, 2 * FFI), 256>>>(ln, ff1_w, ff1_b, nullptr, ffh, HW, 2 * FFI, CCH);
    geglu_kernel<<<(HW * FFI + 255) / 256, 256>>>(ffh, gg);
    sgemm_kernel<false, false><<<gemm_grid(HW, CCH), 256>>>(gg, ff2_w, ff2_b, res, res, HW, CCH, FFI);

    // 6. proj_out (conv1x1) + input residual
    sgemm_kernel<true, true><<<gemm_grid(CCH, HW), 256>>>(pout_w, res, pout_b, x, out, CCH, HW, CCH);
}

// round 5
// speedup vs baseline: 1.8058x; 1.8058x over previous
#include <cuda_runtime.h>
#include <math.h>
#include <stdint.h>

// ---------------------------------------------------------------------------
// SpatialTransformer: tf32 mma.sync GEMMs + restructured SIMT flash attention.
// ---------------------------------------------------------------------------

#define HW    4096
#define CCH   320
#define GROUPS 32
#define CPG   10
#define HEADS 8
#define DH    40
#define CTXN  77
#define CTXD  768
#define FFI   1280

__device__ float g_mu[GROUPS], g_rs[GROUPS];
__device__ float g_gnA[HW * CCH];
__device__ float g_res[HW * CCH];
__device__ float g_ln[HW * CCH];
__device__ float g_q[HW * CCH];
__device__ float g_k[HW * CCH];
__device__ float g_v[HW * CCH];
__device__ float g_attn[HW * CCH];
__device__ float g_ffh[HW * 2 * FFI];
__device__ float g_gg[HW * FFI];
__device__ float g_kc[CTXN * CCH];
__device__ float g_vc[CTXN * CCH];

// ---------------------------------------------------------------------------
// GroupNorm stats
// ---------------------------------------------------------------------------
__global__ void gn_stats_kernel(const float* __restrict__ x) {
    int g = blockIdx.x;
    int tid = threadIdx.x;                 // 256
    const float* xg = x + (size_t)g * CPG * HW;
    float s = 0.f, s2 = 0.f;
    for (int i = tid; i < CPG * HW; i += 256) {
        float v = xg[i];
        s += v; s2 += v * v;
    }
    __shared__ float r1[8], r2[8];
    int lane = tid & 31, wp = tid >> 5;
    #pragma unroll
    for (int o = 16; o; o >>= 1) {
        s  += __shfl_xor_sync(0xffffffffu, s,  o);
        s2 += __shfl_xor_sync(0xffffffffu, s2, o);
    }
    if (lane == 0) { r1[wp] = s; r2[wp] = s2; }
    __syncthreads();
    if (tid == 0) {
        float t = 0.f, t2 = 0.f;
        for (int i = 0; i < 8; i++) { t += r1[i]; t2 += r2[i]; }
        float inv = 1.f / (float)(CPG * HW);
        float mean = t * inv;
        float var  = t2 * inv - mean * mean;
        g_mu[g] = mean;
        g_rs[g] = rsqrtf(var + 1e-6f);
    }
}

// ---------------------------------------------------------------------------
// GroupNorm apply + transpose
// ---------------------------------------------------------------------------
__global__ void gn_apply_kernel(const float* __restrict__ x, const float* __restrict__ w,
                                const float* __restrict__ b, float* __restrict__ o) {
    __shared__ float tile[32][33];
    int n0 = blockIdx.x * 32, c0 = blockIdx.y * 32;
    int tx = threadIdx.x, ty = threadIdx.y;  // 32 x 8
    for (int r = ty; r < 32; r += 8)
        tile[r][tx] = x[(size_t)(c0 + r) * HW + n0 + tx];
    __syncthreads();
    for (int r = ty; r < 32; r += 8) {
        int c = c0 + tx, n = n0 + r;
        int g = c / CPG;
        o[(size_t)n * CCH + c] = (tile[tx][r] - g_mu[g]) * g_rs[g] * w[c] + b[c];
    }
}

// ---------------------------------------------------------------------------
// tf32 helpers
// ---------------------------------------------------------------------------
__device__ __forceinline__ uint32_t f2tf(float f) {
    uint32_t u;
    asm("cvt.rna.tf32.f32 %0, %1;" : "=r"(u) : "f"(f));
    return u;
}

__device__ __forceinline__ void mma_tf32(float c[4],
        uint32_t a0, uint32_t a1, uint32_t a2, uint32_t a3,
        uint32_t b0, uint32_t b1) {
    asm volatile(
        "mma.sync.aligned.m16n8k8.row.col.f32.tf32.tf32.f32 "
        "{%0,%1,%2,%3},{%4,%5,%6,%7},{%8,%9},{%0,%1,%2,%3};"
        : "+f"(c[0]), "+f"(c[1]), "+f"(c[2]), "+f"(c[3])
        : "r"(a0), "r"(a1), "r"(a2), "r"(a3), "r"(b0), "r"(b1));
}

// ---------------------------------------------------------------------------
// tf32 tensor-core GEMM: C[M,N] = A[M,K] * B (+bias) (+resid)
//   TB=false: B is [K,N].  TB=true: B is [N,K].
//   gridDim.z selects (Bz, Cz) for fused multi-weight launches.
// Block: 256 thr (8 warps), tile 128x128, warp tile 64x32, k-step 8.
// Requires K % 8 == 0.
// ---------------------------------------------------------------------------
template <bool TB, bool BIAS_ROW>
__global__ __launch_bounds__(256) void mgemm_kernel(
        const float* __restrict__ A,
        const float* __restrict__ B0, const float* __restrict__ B1, const float* __restrict__ B2,
        const float* __restrict__ bias, const float* __restrict__ resid,
        float* __restrict__ C0, float* __restrict__ C1, float* __restrict__ C2,
        int M, int N, int K) {
    const float* B = (blockIdx.z == 0) ? B0 : (blockIdx.z == 1) ? B1 : B2;
    float*       C = (blockIdx.z == 0) ? C0 : (blockIdx.z == 1) ? C1 : C2;

    __shared__ uint32_t As[128 * 9];   // As[m][k], stride 9
    __shared__ uint32_t Bs[128 * 9];   // Bs[n][k], stride 9

    const int bm = blockIdx.y * 128, bn = blockIdx.x * 128;
    const int tid = threadIdx.x;
    const int lane = tid & 31;
    const int w = tid >> 5;            // 0..7
    const int m_off = (w >> 2) * 64;   // 0,64
    const int n_off = (w & 3) * 32;    // 0..96

    // loader indices
    const int arow = tid >> 1;         // 0..127
    const int akq  = (tid & 1) * 4;
    const int bkr  = tid >> 5;         // 0..7  (TB=false)
    const int bnq  = (tid & 31) * 4;
    const int bnr  = tid >> 1;         // (TB=true)
    const int bkq  = (tid & 1) * 4;

    float acc[4][4][4];
    #pragma unroll
    for (int i = 0; i < 4; i++)
        #pragma unroll
        for (int j = 0; j < 4; j++)
            #pragma unroll
            for (int r = 0; r < 4; r++) acc[i][j][r] = 0.f;

    for (int k0 = 0; k0 < K; k0 += 8) {
        // A tile
        {
            int gm = bm + arow;
            float4 v = make_float4(0.f, 0.f, 0.f, 0.f);
            if (gm < M) v = *(const float4*)(A + (size_t)gm * K + k0 + akq);
            As[arow * 9 + akq + 0] = f2tf(v.x);
            As[arow * 9 + akq + 1] = f2tf(v.y);
            As[arow * 9 + akq + 2] = f2tf(v.z);
            As[arow * 9 + akq + 3] = f2tf(v.w);
        }
        // B tile -> Bs[n][k]
        if (!TB) {
            int gn = bn + bnq;
            float4 v;
            if (gn + 3 < N) {
                v = *(const float4*)(B + (size_t)(k0 + bkr) * N + gn);
            } else {
                v.x = (gn + 0 < N) ? B[(size_t)(k0 + bkr) * N + gn + 0] : 0.f;
                v.y = (gn + 1 < N) ? B[(size_t)(k0 + bkr) * N + gn + 1] : 0.f;
                v.z = (gn + 2 < N) ? B[(size_t)(k0 + bkr) * N + gn + 2] : 0.f;
                v.w = 0.f;
            }
            Bs[(bnq + 0) * 9 + bkr] = f2tf(v.x);
            Bs[(bnq + 1) * 9 + bkr] = f2tf(v.y);
            Bs[(bnq + 2) * 9 + bkr] = f2tf(v.z);
            Bs[(bnq + 3) * 9 + bkr] = f2tf(v.w);
        } else {
            int gn = bn + bnr;
            float4 v = make_float4(0.f, 0.f, 0.f, 0.f);
            if (gn < N) v = *(const float4*)(B + (size_t)gn * K + k0 + bkq);
            Bs[bnr * 9 + bkq + 0] = f2tf(v.x);
            Bs[bnr * 9 + bkq + 1] = f2tf(v.y);
            Bs[bnr * 9 + bkq + 2] = f2tf(v.z);
            Bs[bnr * 9 + bkq + 3] = f2tf(v.w);
        }
        __syncthreads();

        // fragments
        uint32_t af[4][4], bf[4][2];
        const int fq = lane >> 2;      // 0..7
        const int fr = lane & 3;       // 0..3
        #pragma unroll
        for (int mt = 0; mt < 4; mt++) {
            int row = m_off + mt * 16 + fq;
            af[mt][0] = As[row * 9 + fr];
            af[mt][1] = As[(row + 8) * 9 + fr];
            af[mt][2] = As[row * 9 + fr + 4];
            af[mt][3] = As[(row + 8) * 9 + fr + 4];
        }
        #pragma unroll
        for (int nt = 0; nt < 4; nt++) {
            int col = n_off + nt * 8 + fq;
            bf[nt][0] = Bs[col * 9 + fr];
            bf[nt][1] = Bs[col * 9 + fr + 4];
        }
        #pragma unroll
        for (int mt = 0; mt < 4; mt++)
            #pragma unroll
            for (int nt = 0; nt < 4; nt++)
                mma_tf32(acc[mt][nt], af[mt][0], af[mt][1], af[mt][2], af[mt][3],
                         bf[nt][0], bf[nt][1]);
        __syncthreads();
    }

    // epilogue
    const int fq = lane >> 2;
    const int fr = lane & 3;
    #pragma unroll
    for (int mt = 0; mt < 4; mt++) {
        #pragma unroll
        for (int nt = 0; nt < 4; nt++) {
            #pragma unroll
            for (int r = 0; r < 4; r++) {
                int gm = bm + m_off + mt * 16 + fq + (r >= 2 ? 8 : 0);
                int gn = bn + n_off + nt * 8 + 2 * fr + (r & 1);
                if (gm >= M || gn >= N) continue;
                float v = acc[mt][nt][r];
                if (bias)  v += BIAS_ROW ? bias[gm] : bias[gn];
                if (resid) v += resid[(size_t)gm * N + gn];
                C[(size_t)gm * N + gn] = v;
            }
        }
    }
}

// ---------------------------------------------------------------------------
// LayerNorm over last dim 320
// ---------------------------------------------------------------------------
__global__ void ln_kernel(const float* __restrict__ x, const float* __restrict__ w,
                          const float* __restrict__ b, float* __restrict__ y) {
    int row = blockIdx.x;
    int tid = threadIdx.x;                 // 320
    float v = x[(size_t)row * CCH + tid];
    __shared__ float red[10];
    __shared__ float s_mean, s_rstd;
    int lane = tid & 31, wp = tid >> 5;
    float s = v;
    #pragma unroll
    for (int o = 16; o; o >>= 1) s += __shfl_xor_sync(0xffffffffu, s, o);
    if (lane == 0) red[wp] = s;
    __syncthreads();
    if (tid == 0) {
        float t = 0.f;
        for (int i = 0; i < 10; i++) t += red[i];
        s_mean = t / (float)CCH;
    }
    __syncthreads();
    float d = v - s_mean;
    s = d * d;
    #pragma unroll
    for (int o = 16; o; o >>= 1) s += __shfl_xor_sync(0xffffffffu, s, o);
    if (lane == 0) red[wp] = s;
    __syncthreads();
    if (tid == 0) {
        float t = 0.f;
        for (int i = 0; i < 10; i++) t += red[i];
        s_rstd = rsqrtf(t / (float)CCH + 1e-5f);
    }
    __syncthreads();
    y[(size_t)row * CCH + tid] = d * s_rstd * w[tid] + b[tid];
}

// ---------------------------------------------------------------------------
// Flash attention, 128 threads, 64 queries x 1 head per block.
// smem: Qt[64][41], Kt[64][44], Vt[64][40], P[64][65] (col64 = alpha), s_m, s_l
// QK: 4q x 8k micro-tile (k strided: kg + 8j), float4 K loads.
// PV: 4q x 5d micro-tile.
// ---------------------------------------------------------------------------
#define QTS 41
#define KTS 44
#define VTS 40
#define PS  65

__global__ __launch_bounds__(128) void attn_kernel(
    const float* __restrict__ Q, const float* __restrict__ K,
    const float* __restrict__ V, float* __restrict__ O, int Mk) {
    __shared__ float sm[12288];   // exactly 48KB
    float* Qt  = sm;                    // 64*41 = 2624
    float* Kt  = Qt + 64 * QTS;         // 64*44 = 2816
    float* Vt  = Kt + 64 * KTS;         // 64*40 = 2560
    float* P   = Vt + 64 * VTS;         // 64*65 = 4160
    float* s_m = P + 64 * PS;           // 64
    float* s_l = s_m + 64;              // 64

    const int tid = threadIdx.x;
    const int h = blockIdx.y;
    const int q0 = blockIdx.x * 64;
    const int off = h * DH;
    const float scale = 0.15811388300841898f;

    // fill Q (scalar, coalesced by row-chunks)
    for (int i = tid; i < 64 * DH; i += 128) {
        int r = i / DH, c = i % DH;
        Qt[r * QTS + c] = Q[(size_t)(q0 + r) * CCH + off + c];
    }
    if (tid < 64) { s_m[tid] = -INFINITY; s_l[tid] = 0.f; }

    const int qg = tid >> 3;   // 0..15  (4 q-rows each)
    const int kg = tid & 7;    // 0..7   (8 strided k-cols each)
    const int dg = tid & 7;    // 0..7   (5 d-cols each)

    float acc[4][5];
    #pragma unroll
    for (int i = 0; i < 4; i++)
        #pragma unroll
        for (int j = 0; j < 5; j++) acc[i][j] = 0.f;

    __syncthreads();

    for (int kb = 0; kb < Mk; kb += 64) {
        const int nk = min(64, Mk - kb);
        // fill K (float4), V (float4)
        for (int i = tid; i < 64 * 10; i += 128) {
            int r = i / 10, cq = (i % 10) * 4;
            float4 kv = make_float4(0.f, 0.f, 0.f, 0.f);
            float4 vv = make_float4(0.f, 0.f, 0.f, 0.f);
            if (r < nk) {
                kv = *(const float4*)(K + (size_t)(kb + r) * CCH + off + cq);
                vv = *(const float4*)(V + (size_t)(kb + r) * CCH + off + cq);
            }
            *(float4*)(Kt + r * KTS + cq) = kv;
            *(float4*)(Vt + r * VTS + cq) = vv;
        }
        __syncthreads();

        // ---- QK^T: s[4][8], k columns = kg + 8j ----
        float s[4][8];
        #pragma unroll
        for (int i = 0; i < 4; i++)
            #pragma unroll
            for (int j = 0; j < 8; j++) s[i][j] = 0.f;
        #pragma unroll
        for (int c4 = 0; c4 < 10; c4++) {
            float4 kv[8];
            #pragma unroll
            for (int j = 0; j < 8; j++)
                kv[j] = *(const float4*)(Kt + (kg + 8 * j) * KTS + c4 * 4);
            #pragma unroll
            for (int cc = 0; cc < 4; cc++) {
                float qv[4];
                #pragma unroll
                for (int i = 0; i < 4; i++)
                    qv[i] = Qt[(qg * 4 + i) * QTS + c4 * 4 + cc];
                #pragma unroll
                for (int i = 0; i < 4; i++) {
                    float q = qv[i];
                    #pragma unroll
                    for (int j = 0; j < 8; j++) {
                        float kvv = (cc == 0) ? kv[j].x : (cc == 1) ? kv[j].y
                                  : (cc == 2) ? kv[j].z : kv[j].w;
                        s[i][j] += q * kvv;
                    }
                }
            }
        }
        #pragma unroll
        for (int i = 0; i < 4; i++)
            #pragma unroll
            for (int j = 0; j < 8; j++) {
                int k = kg + 8 * j;
                P[(qg * 4 + i) * PS + k] = (k < nk) ? s[i][j] * scale : -INFINITY;
            }
        __syncthreads();

        // ---- online softmax: 2 threads per row ----
        {
            int r = tid >> 1, hh = tid & 1;
            int base = r * PS + hh * 32;
            float mx = -INFINITY;
            #pragma unroll
            for (int j = 0; j < 32; j++) mx = fmaxf(mx, P[base + j]);
            mx = fmaxf(mx, __shfl_xor_sync(0xffffffffu, mx, 1));
            float mold = s_m[r];
            float mnew = fmaxf(mold, mx);
            float sum = 0.f;
            #pragma unroll
            for (int j = 0; j < 32; j++) {
                float p = __expf(P[base + j] - mnew);
                P[base + j] = p;
                sum += p;
            }
            sum += __shfl_xor_sync(0xffffffffu, sum, 1);
            if (hh == 0) {
                float al = __expf(mold - mnew);
                s_l[r] = s_l[r] * al + sum;
                s_m[r] = mnew;
                P[r * PS + 64] = al;   // stash alpha in pad column
            }
        }
        __syncthreads();

        // ---- P @ V: 4q x 5d ----
        float al[4];
        #pragma unroll
        for (int i = 0; i < 4; i++) al[i] = P[(qg * 4 + i) * PS + 64];
        #pragma unroll
        for (int i = 0; i < 4; i++)
            #pragma unroll
            for (int j = 0; j < 5; j++) acc[i][j] *= al[i];
        for (int k = 0; k < nk; k++) {
            float p[4];
            #pragma unroll
            for (int i = 0; i < 4; i++) p[i] = P[(qg * 4 + i) * PS + k];
            float vv[5];
            #pragma unroll
            for (int j = 0; j < 5; j++) vv[j] = Vt[k * VTS + dg * 5 + j];
            #pragma unroll
            for (int i = 0; i < 4; i++)
                #pragma unroll
                for (int j = 0; j < 5; j++) acc[i][j] += p[i] * vv[j];
        }
        __syncthreads();
    }

    #pragma unroll
    for (int i = 0; i < 4; i++) {
        float inv = 1.f / s_l[qg * 4 + i];
        #pragma unroll
        for (int j = 0; j < 5; j++)
            O[(size_t)(q0 + qg * 4 + i) * CCH + off + dg * 5 + j] = acc[i][j] * inv;
    }
}

// ---------------------------------------------------------------------------
// GEGLU
// ---------------------------------------------------------------------------
__global__ void geglu_kernel(const float* __restrict__ h, float* __restrict__ o) {
    int idx = blockIdx.x * blockDim.x + threadIdx.x;
    if (idx >= HW * FFI) return;
    int n = idx / FFI, j = idx % FFI;
    float a = h[(size_t)n * 2 * FFI + j];
    float g = h[(size_t)n * 2 * FFI + FFI + j];
    float ge = 0.5f * g * (1.f + erff(g * 0.70710678118654752f));
    o[idx] = a * ge;
}

// ---------------------------------------------------------------------------
// Host launcher
// ---------------------------------------------------------------------------
static inline dim3 ggrid(int M, int N, int Z) {
    return dim3((N + 127) / 128, (M + 127) / 128, Z);
}

extern "C" void kernel_launch(void* const* d_in, const int* in_sizes, int n_in,
                              void* d_out, int out_size) {
    const float* x       = (const float*)d_in[0];
    const float* context = (const float*)d_in[1];
    const float* gn_w    = (const float*)d_in[2];
    const float* gn_b    = (const float*)d_in[3];
    const float* pin_w   = (const float*)d_in[4];
    const float* pin_b   = (const float*)d_in[5];
    const float* ln1_w   = (const float*)d_in[6];
    const float* ln1_b   = (const float*)d_in[7];
    const float* q1      = (const float*)d_in[8];
    const float* k1      = (const float*)d_in[9];
    const float* v1      = (const float*)d_in[10];
    const float* o1_w    = (const float*)d_in[11];
    const float* o1_b    = (const float*)d_in[12];
    const float* ln2_w   = (const float*)d_in[13];
    const float* ln2_b   = (const float*)d_in[14];
    const float* q2      = (const float*)d_in[15];
    const float* k2      = (const float*)d_in[16];
    const float* v2      = (const float*)d_in[17];
    const float* o2_w    = (const float*)d_in[18];
    const float* o2_b    = (const float*)d_in[19];
    const float* ln3_w   = (const float*)d_in[20];
    const float* ln3_b   = (const float*)d_in[21];
    const float* ff1_w   = (const float*)d_in[22];
    const float* ff1_b   = (const float*)d_in[23];
    const float* ff2_w   = (const float*)d_in[24];
    const float* ff2_b   = (const float*)d_in[25];
    const float* pout_w  = (const float*)d_in[26];
    const float* pout_b  = (const float*)d_in[27];
    float* out = (float*)d_out;

    float *gnA, *res, *ln, *q, *k, *v, *attn, *ffh, *gg, *kc, *vc;
    cudaGetSymbolAddress((void**)&gnA,  g_gnA);
    cudaGetSymbolAddress((void**)&res,  g_res);
    cudaGetSymbolAddress((void**)&ln,   g_ln);
    cudaGetSymbolAddress((void**)&q,    g_q);
    cudaGetSymbolAddress((void**)&k,    g_k);
    cudaGetSymbolAddress((void**)&v,    g_v);
    cudaGetSymbolAddress((void**)&attn, g_attn);
    cudaGetSymbolAddress((void**)&ffh,  g_ffh);
    cudaGetSymbolAddress((void**)&gg,   g_gg);
    cudaGetSymbolAddress((void**)&kc,   g_kc);
    cudaGetSymbolAddress((void**)&vc,   g_vc);

    // 1. GroupNorm + transpose
    gn_stats_kernel<<<GROUPS, 256>>>(x);
    gn_apply_kernel<<<dim3(HW / 32, CCH / 32), dim3(32, 8)>>>(x, gn_w, gn_b, gnA);

    // 2. proj_in: res = gnA @ pin_w^T + pin_b
    mgemm_kernel<true, false><<<ggrid(HW, CCH, 1), 256>>>(
        gnA, pin_w, pin_w, pin_w, pin_b, nullptr, res, res, res, HW, CCH, CCH);

    // 3. self-attention block
    ln_kernel<<<HW, CCH>>>(res, ln1_w, ln1_b, ln);
    mgemm_kernel<false, false><<<ggrid(HW, CCH, 3), 256>>>(
        ln, q1, k1, v1, nullptr, nullptr, q, k, v, HW, CCH, CCH);
    attn_kernel<<<dim3(HW / 64, HEADS), 128>>>(q, k, v, attn, HW);
    mgemm_kernel<false, false><<<ggrid(HW, CCH, 1), 256>>>(
        attn, o1_w, o1_w, o1_w, o1_b, res, res, res, res, HW, CCH, CCH);

    // 4. cross-attention block
    ln_kernel<<<HW, CCH>>>(res, ln2_w, ln2_b, ln);
    mgemm_kernel<false, false><<<ggrid(HW, CCH, 1), 256>>>(
        ln, q2, q2, q2, nullptr, nullptr, q, q, q, HW, CCH, CCH);
    mgemm_kernel<false, false><<<ggrid(CTXN, CCH, 2), 256>>>(
        context, k2, v2, v2, nullptr, nullptr, kc, vc, vc, CTXN, CCH, CTXD);
    attn_kernel<<<dim3(HW / 64, HEADS), 128>>>(q, kc, vc, attn, CTXN);
    mgemm_kernel<false, false><<<ggrid(HW, CCH, 1), 256>>>(
        attn, o2_w, o2_w, o2_w, o2_b, res, res, res, res, HW, CCH, CCH);

    // 5. GEGLU FF
    ln_kernel<<<HW, CCH>>>(res, ln3_w, ln3_b, ln);
    mgemm_kernel<false, false><<<ggrid(HW, 2 * FFI, 1), 256>>>(
        ln, ff1_w, ff1_w, ff1_w, ff1_b, nullptr, ffh, ffh, ffh, HW, 2 * FFI, CCH);
    geglu_kernel<<<(HW * FFI + 255) / 256, 256>>>(ffh, gg);
    mgemm_kernel<false, false><<<ggrid(HW, CCH, 1), 256>>>(
        gg, ff2_w, ff2_w, ff2_w, ff2_b, res, res, res, res, HW, CCH, FFI);

    // 6. proj_out + input residual: out[c][hw]
    mgemm_kernel<true, true><<<ggrid(CCH, HW, 1), 256>>>(
        pout_w, res, res, res, pout_b, x, out, out, out, CCH, HW, CCH);
}

// round 7
// speedup vs baseline: 2.2385x; 1.2396x over previous
#include <cuda_runtime.h>
#include <math.h>
#include <stdint.h>

// ---------------------------------------------------------------------------
// SpatialTransformer: tf32 mma.sync GEMMs + tf32 mma flash attention.
// ---------------------------------------------------------------------------

#define HW    4096
#define CCH   320
#define GROUPS 32
#define CPG   10
#define HEADS 8
#define DH    40
#define CTXN  77
#define CTXD  768
#define FFI   1280

__device__ float g_mu[GROUPS], g_rs[GROUPS];
__device__ float g_gnA[HW * CCH];
__device__ float g_res[HW * CCH];
__device__ float g_ln[HW * CCH];
__device__ float g_q[HW * CCH];
__device__ float g_k[HW * CCH];
__device__ float g_v[HW * CCH];
__device__ float g_attn[HW * CCH];
__device__ float g_ffh[HW * 2 * FFI];
__device__ float g_gg[HW * FFI];
__device__ float g_kc[CTXN * CCH];
__device__ float g_vc[CTXN * CCH];

// ---------------------------------------------------------------------------
// GroupNorm stats
// ---------------------------------------------------------------------------
__global__ void gn_stats_kernel(const float* __restrict__ x) {
    int g = blockIdx.x;
    int tid = threadIdx.x;                 // 256
    const float* xg = x + (size_t)g * CPG * HW;
    float s = 0.f, s2 = 0.f;
    for (int i = tid; i < CPG * HW; i += 256) {
        float v = xg[i];
        s += v; s2 += v * v;
    }
    __shared__ float r1[8], r2[8];
    int lane = tid & 31, wp = tid >> 5;
    #pragma unroll
    for (int o = 16; o; o >>= 1) {
        s  += __shfl_xor_sync(0xffffffffu, s,  o);
        s2 += __shfl_xor_sync(0xffffffffu, s2, o);
    }
    if (lane == 0) { r1[wp] = s; r2[wp] = s2; }
    __syncthreads();
    if (tid == 0) {
        float t = 0.f, t2 = 0.f;
        for (int i = 0; i < 8; i++) { t += r1[i]; t2 += r2[i]; }
        float inv = 1.f / (float)(CPG * HW);
        float mean = t * inv;
        float var  = t2 * inv - mean * mean;
        g_mu[g] = mean;
        g_rs[g] = rsqrtf(var + 1e-6f);
    }
}

// ---------------------------------------------------------------------------
// GroupNorm apply + transpose
// ---------------------------------------------------------------------------
__global__ void gn_apply_kernel(const float* __restrict__ x, const float* __restrict__ w,
                                const float* __restrict__ b, float* __restrict__ o) {
    __shared__ float tile[32][33];
    int n0 = blockIdx.x * 32, c0 = blockIdx.y * 32;
    int tx = threadIdx.x, ty = threadIdx.y;  // 32 x 8
    for (int r = ty; r < 32; r += 8)
        tile[r][tx] = x[(size_t)(c0 + r) * HW + n0 + tx];
    __syncthreads();
    for (int r = ty; r < 32; r += 8) {
        int c = c0 + tx, n = n0 + r;
        int g = c / CPG;
        o[(size_t)n * CCH + c] = (tile[tx][r] - g_mu[g]) * g_rs[g] * w[c] + b[c];
    }
}

// ---------------------------------------------------------------------------
// tf32 helpers
// ---------------------------------------------------------------------------
__device__ __forceinline__ uint32_t f2tf(float f) {
    uint32_t u;
    asm("cvt.rna.tf32.f32 %0, %1;" : "=r"(u) : "f"(f));
    return u;
}

__device__ __forceinline__ void mma_tf32(float c[4],
        uint32_t a0, uint32_t a1, uint32_t a2, uint32_t a3,
        uint32_t b0, uint32_t b1) {
    asm volatile(
        "mma.sync.aligned.m16n8k8.row.col.f32.tf32.tf32.f32 "
        "{%0,%1,%2,%3},{%4,%5,%6,%7},{%8,%9},{%0,%1,%2,%3};"
        : "+f"(c[0]), "+f"(c[1]), "+f"(c[2]), "+f"(c[3])
        : "r"(a0), "r"(a1), "r"(a2), "r"(a3), "r"(b0), "r"(b1));
}

// ---------------------------------------------------------------------------
// tf32 tensor-core GEMM (proven in R5): C[M,N] = A[M,K] * B (+bias) (+resid)
// ---------------------------------------------------------------------------
template <bool TB, bool BIAS_ROW>
__global__ __launch_bounds__(256) void mgemm_kernel(
        const float* __restrict__ A,
        const float* __restrict__ B0, const float* __restrict__ B1, const float* __restrict__ B2,
        const float* __restrict__ bias, const float* __restrict__ resid,
        float* __restrict__ C0, float* __restrict__ C1, float* __restrict__ C2,
        int M, int N, int K) {
    const float* B = (blockIdx.z == 0) ? B0 : (blockIdx.z == 1) ? B1 : B2;
    float*       C = (blockIdx.z == 0) ? C0 : (blockIdx.z == 1) ? C1 : C2;

    __shared__ uint32_t As[128 * 9];
    __shared__ uint32_t Bs[128 * 9];

    const int bm = blockIdx.y * 128, bn = blockIdx.x * 128;
    const int tid = threadIdx.x;
    const int lane = tid & 31;
    const int w = tid >> 5;
    const int m_off = (w >> 2) * 64;
    const int n_off = (w & 3) * 32;

    const int arow = tid >> 1;
    const int akq  = (tid & 1) * 4;
    const int bkr  = tid >> 5;
    const int bnq  = (tid & 31) * 4;
    const int bnr  = tid >> 1;
    const int bkq  = (tid & 1) * 4;

    float acc[4][4][4];
    #pragma unroll
    for (int i = 0; i < 4; i++)
        #pragma unroll
        for (int j = 0; j < 4; j++)
            #pragma unroll
            for (int r = 0; r < 4; r++) acc[i][j][r] = 0.f;

    for (int k0 = 0; k0 < K; k0 += 8) {
        {
            int gm = bm + arow;
            float4 v = make_float4(0.f, 0.f, 0.f, 0.f);
            if (gm < M) v = *(const float4*)(A + (size_t)gm * K + k0 + akq);
            As[arow * 9 + akq + 0] = f2tf(v.x);
            As[arow * 9 + akq + 1] = f2tf(v.y);
            As[arow * 9 + akq + 2] = f2tf(v.z);
            As[arow * 9 + akq + 3] = f2tf(v.w);
        }
        if (!TB) {
            int gn = bn + bnq;
            float4 v;
            if (gn + 3 < N) {
                v = *(const float4*)(B + (size_t)(k0 + bkr) * N + gn);
            } else {
                v.x = (gn + 0 < N) ? B[(size_t)(k0 + bkr) * N + gn + 0] : 0.f;
                v.y = (gn + 1 < N) ? B[(size_t)(k0 + bkr) * N + gn + 1] : 0.f;
                v.z = (gn + 2 < N) ? B[(size_t)(k0 + bkr) * N + gn + 2] : 0.f;
                v.w = 0.f;
            }
            Bs[(bnq + 0) * 9 + bkr] = f2tf(v.x);
            Bs[(bnq + 1) * 9 + bkr] = f2tf(v.y);
            Bs[(bnq + 2) * 9 + bkr] = f2tf(v.z);
            Bs[(bnq + 3) * 9 + bkr] = f2tf(v.w);
        } else {
            int gn = bn + bnr;
            float4 v = make_float4(0.f, 0.f, 0.f, 0.f);
            if (gn < N) v = *(const float4*)(B + (size_t)gn * K + k0 + bkq);
            Bs[bnr * 9 + bkq + 0] = f2tf(v.x);
            Bs[bnr * 9 + bkq + 1] = f2tf(v.y);
            Bs[bnr * 9 + bkq + 2] = f2tf(v.z);
            Bs[bnr * 9 + bkq + 3] = f2tf(v.w);
        }
        __syncthreads();

        uint32_t af[4][4], bf[4][2];
        const int fq = lane >> 2;
        const int fr = lane & 3;
        #pragma unroll
        for (int mt = 0; mt < 4; mt++) {
            int row = m_off + mt * 16 + fq;
            af[mt][0] = As[row * 9 + fr];
            af[mt][1] = As[(row + 8) * 9 + fr];
            af[mt][2] = As[row * 9 + fr + 4];
            af[mt][3] = As[(row + 8) * 9 + fr + 4];
        }
        #pragma unroll
        for (int nt = 0; nt < 4; nt++) {
            int col = n_off + nt * 8 + fq;
            bf[nt][0] = Bs[col * 9 + fr];
            bf[nt][1] = Bs[col * 9 + fr + 4];
        }
        #pragma unroll
        for (int mt = 0; mt < 4; mt++)
            #pragma unroll
            for (int nt = 0; nt < 4; nt++)
                mma_tf32(acc[mt][nt], af[mt][0], af[mt][1], af[mt][2], af[mt][3],
                         bf[nt][0], bf[nt][1]);
        __syncthreads();
    }

    const int fq = lane >> 2;
    const int fr = lane & 3;
    #pragma unroll
    for (int mt = 0; mt < 4; mt++) {
        #pragma unroll
        for (int nt = 0; nt < 4; nt++) {
            #pragma unroll
            for (int r = 0; r < 4; r++) {
                int gm = bm + m_off + mt * 16 + fq + (r >= 2 ? 8 : 0);
                int gn = bn + n_off + nt * 8 + 2 * fr + (r & 1);
                if (gm >= M || gn >= N) continue;
                float v = acc[mt][nt][r];
                if (bias)  v += BIAS_ROW ? bias[gm] : bias[gn];
                if (resid) v += resid[(size_t)gm * N + gn];
                C[(size_t)gm * N + gn] = v;
            }
        }
    }
}

// ---------------------------------------------------------------------------
// LayerNorm over last dim 320
// ---------------------------------------------------------------------------
__global__ void ln_kernel(const float* __restrict__ x, const float* __restrict__ w,
                          const float* __restrict__ b, float* __restrict__ y) {
    int row = blockIdx.x;
    int tid = threadIdx.x;                 // 320
    float v = x[(size_t)row * CCH + tid];
    __shared__ float red[10];
    __shared__ float s_mean, s_rstd;
    int lane = tid & 31, wp = tid >> 5;
    float s = v;
    #pragma unroll
    for (int o = 16; o; o >>= 1) s += __shfl_xor_sync(0xffffffffu, s, o);
    if (lane == 0) red[wp] = s;
    __syncthreads();
    if (tid == 0) {
        float t = 0.f;
        for (int i = 0; i < 10; i++) t += red[i];
        s_mean = t / (float)CCH;
    }
    __syncthreads();
    float d = v - s_mean;
    s = d * d;
    #pragma unroll
    for (int o = 16; o; o >>= 1) s += __shfl_xor_sync(0xffffffffu, s, o);
    if (lane == 0) red[wp] = s;
    __syncthreads();
    if (tid == 0) {
        float t = 0.f;
        for (int i = 0; i < 10; i++) t += red[i];
        s_rstd = rsqrtf(t / (float)CCH + 1e-5f);
    }
    __syncthreads();
    y[(size_t)row * CCH + tid] = d * s_rstd * w[tid] + b[tid];
}

// ---------------------------------------------------------------------------
// tf32 mma flash attention. 128 threads (4 warps), 64 queries x 1 head.
// Warp w owns q-rows [w*16, w*16+16).
// Ks/Vs: [key][dim] tf32, stride 44 (44%32=12 -> conflict-free fragments).
// P: [q][key] float, stride 68 (68%32=4 -> conflict-free fragment/stores).
// Q fragments loop-invariant in registers, scale folded.
// PV B-fragment = Vs[k*SK + n] (no physical transpose: B[n][k]=V[key][dim]).
// ---------------------------------------------------------------------------
#define SK 44
#define SP 68

__global__ __launch_bounds__(128) void attn_kernel(
    const float* __restrict__ Q, const float* __restrict__ K,
    const float* __restrict__ V, float* __restrict__ O, int Mk) {
    __shared__ uint32_t Ks[64 * SK];
    __shared__ uint32_t Vs[64 * SK];
    __shared__ float P[64 * SP];
    __shared__ float s_m[64], s_l[64], s_al[64];

    const int tid = threadIdx.x;
    const int lane = tid & 31;
    const int w = tid >> 5;
    const int m_off = w * 16;
    const int fq = lane >> 2;      // 0..7
    const int fr = lane & 3;       // 0..3
    const int h = blockIdx.y;
    const int q0 = blockIdx.x * 64;
    const int off = h * DH;
    const float scale = 0.15811388300841898f;  // 40^-0.5

    // Q fragments: loop-invariant, scale folded. Rows q0+m_off+fq, +8.
    uint32_t qf[5][4];
    {
        const float* Qr0 = Q + (size_t)(q0 + m_off + fq) * CCH + off;
        const float* Qr1 = Qr0 + 8 * CCH;
        #pragma unroll
        for (int ks = 0; ks < 5; ks++) {
            qf[ks][0] = f2tf(Qr0[ks * 8 + fr] * scale);
            qf[ks][1] = f2tf(Qr1[ks * 8 + fr] * scale);
            qf[ks][2] = f2tf(Qr0[ks * 8 + fr + 4] * scale);
            qf[ks][3] = f2tf(Qr1[ks * 8 + fr + 4] * scale);
        }
    }
    if (tid < 64) { s_m[tid] = -INFINITY; s_l[tid] = 0.f; }

    float acc_o[5][4];
    #pragma unroll
    for (int nt = 0; nt < 5; nt++)
        #pragma unroll
        for (int r = 0; r < 4; r++) acc_o[nt][r] = 0.f;

    for (int kb = 0; kb < Mk; kb += 64) {
        const int nk = min(64, Mk - kb);
        // stage K, V as tf32 [key][dim]
        for (int i = tid; i < 640; i += 128) {
            int r = i / 10, cq = (i % 10) * 4;
            float4 kv = make_float4(0.f, 0.f, 0.f, 0.f);
            float4 vv = make_float4(0.f, 0.f, 0.f, 0.f);
            if (r < nk) {
                kv = *(const float4*)(K + (size_t)(kb + r) * CCH + off + cq);
                vv = *(const float4*)(V + (size_t)(kb + r) * CCH + off + cq);
            }
            Ks[r * SK + cq + 0] = f2tf(kv.x);
            Ks[r * SK + cq + 1] = f2tf(kv.y);
            Ks[r * SK + cq + 2] = f2tf(kv.z);
            Ks[r * SK + cq + 3] = f2tf(kv.w);
            Vs[r * SK + cq + 0] = f2tf(vv.x);
            Vs[r * SK + cq + 1] = f2tf(vv.y);
            Vs[r * SK + cq + 2] = f2tf(vv.z);
            Vs[r * SK + cq + 3] = f2tf(vv.w);
        }
        __syncthreads();

        // ---- QK^T: m16 (warp rows) x n64 (keys) x k40 (dims) ----
        float s[8][4];
        #pragma unroll
        for (int nt = 0; nt < 8; nt++)
            #pragma unroll
            for (int r = 0; r < 4; r++) s[nt][r] = 0.f;
        #pragma unroll
        for (int ks = 0; ks < 5; ks++) {
            #pragma unroll
            for (int nt = 0; nt < 8; nt++) {
                uint32_t b0 = Ks[(nt * 8 + fq) * SK + ks * 8 + fr];
                uint32_t b1 = Ks[(nt * 8 + fq) * SK + ks * 8 + fr + 4];
                mma_tf32(s[nt], qf[ks][0], qf[ks][1], qf[ks][2], qf[ks][3], b0, b1);
            }
        }
        // write P (scores; -INF padding for keys >= nk)
        {
            int row0 = (m_off + fq) * SP, row1 = row0 + 8 * SP;
            #pragma unroll
            for (int nt = 0; nt < 8; nt++) {
                int gn = nt * 8 + 2 * fr;
                P[row0 + gn]     = (gn     < nk) ? s[nt][0] : -INFINITY;
                P[row0 + gn + 1] = (gn + 1 < nk) ? s[nt][1] : -INFINITY;
                P[row1 + gn]     = (gn     < nk) ? s[nt][2] : -INFINITY;
                P[row1 + gn + 1] = (gn + 1 < nk) ? s[nt][3] : -INFINITY;
            }
        }
        __syncthreads();

        // ---- online softmax: 2 threads per row ----
        {
            int r = tid >> 1, hh = tid & 1;
            int base = r * SP + hh * 32;
            float mx = -INFINITY;
            #pragma unroll
            for (int j = 0; j < 32; j++) mx = fmaxf(mx, P[base + j]);
            mx = fmaxf(mx, __shfl_xor_sync(0xffffffffu, mx, 1));
            float mold = s_m[r];
            float mnew = fmaxf(mold, mx);
            float sum = 0.f;
            #pragma unroll
            for (int j = 0; j < 32; j++) {
                float p = __expf(P[base + j] - mnew);
                P[base + j] = p;
                sum += p;
            }
            sum += __shfl_xor_sync(0xffffffffu, sum, 1);
            if (hh == 0) {
                float al = __expf(mold - mnew);
                s_l[r] = s_l[r] * al + sum;
                s_m[r] = mnew;
                s_al[r] = al;
            }
        }
        __syncthreads();

        // ---- P @ V: m16 x n40 (dims) x k64 (keys) ----
        {
            float al0 = s_al[m_off + fq], al1 = s_al[m_off + fq + 8];
            #pragma unroll
            for (int nt = 0; nt < 5; nt++) {
                acc_o[nt][0] *= al0; acc_o[nt][1] *= al0;
                acc_o[nt][2] *= al1; acc_o[nt][3] *= al1;
            }
            int row0 = (m_off + fq) * SP, row1 = row0 + 8 * SP;
            #pragma unroll
            for (int kt = 0; kt < 8; kt++) {
                uint32_t pa0 = f2tf(P[row0 + kt * 8 + fr]);
                uint32_t pa1 = f2tf(P[row1 + kt * 8 + fr]);
                uint32_t pa2 = f2tf(P[row0 + kt * 8 + fr + 4]);
                uint32_t pa3 = f2tf(P[row1 + kt * 8 + fr + 4]);
                #pragma unroll
                for (int nt = 0; nt < 5; nt++) {
                    uint32_t b0 = Vs[(kt * 8 + fr) * SK + nt * 8 + fq];
                    uint32_t b1 = Vs[(kt * 8 + fr + 4) * SK + nt * 8 + fq];
                    mma_tf32(acc_o[nt], pa0, pa1, pa2, pa3, b0, b1);
                }
            }
        }
        __syncthreads();
    }

    // epilogue: divide by l, write O
    {
        float inv0 = 1.f / s_l[m_off + fq];
        float inv1 = 1.f / s_l[m_off + fq + 8];
        size_t gm0 = (size_t)(q0 + m_off + fq) * CCH + off;
        size_t gm1 = gm0 + 8 * CCH;
        #pragma unroll
        for (int nt = 0; nt < 5; nt++) {
            int gn = nt * 8 + 2 * fr;
            O[gm0 + gn]     = acc_o[nt][0] * inv0;
            O[gm0 + gn + 1] = acc_o[nt][1] * inv0;
            O[gm1 + gn]     = acc_o[nt][2] * inv1;
            O[gm1 + gn + 1] = acc_o[nt][3] * inv1;
        }
    }
}

// ---------------------------------------------------------------------------
// GEGLU
// ---------------------------------------------------------------------------
__global__ void geglu_kernel(const float* __restrict__ h, float* __restrict__ o) {
    int idx = blockIdx.x * blockDim.x + threadIdx.x;
    if (idx >= HW * FFI) return;
    int n = idx / FFI, j = idx % FFI;
    float a = h[(size_t)n * 2 * FFI + j];
    float g = h[(size_t)n * 2 * FFI + FFI + j];
    float ge = 0.5f * g * (1.f + erff(g * 0.70710678118654752f));
    o[idx] = a * ge;
}

// ---------------------------------------------------------------------------
// Host launcher
// ---------------------------------------------------------------------------
static inline dim3 ggrid(int M, int N, int Z) {
    return dim3((N + 127) / 128, (M + 127) / 128, Z);
}

extern "C" void kernel_launch(void* const* d_in, const int* in_sizes, int n_in,
                              void* d_out, int out_size) {
    const float* x       = (const float*)d_in[0];
    const float* context = (const float*)d_in[1];
    const float* gn_w    = (const float*)d_in[2];
    const float* gn_b    = (const float*)d_in[3];
    const float* pin_w   = (const float*)d_in[4];
    const float* pin_b   = (const float*)d_in[5];
    const float* ln1_w   = (const float*)d_in[6];
    const float* ln1_b   = (const float*)d_in[7];
    const float* q1      = (const float*)d_in[8];
    const float* k1      = (const float*)d_in[9];
    const float* v1      = (const float*)d_in[10];
    const float* o1_w    = (const float*)d_in[11];
    const float* o1_b    = (const float*)d_in[12];
    const float* ln2_w   = (const float*)d_in[13];
    const float* ln2_b   = (const float*)d_in[14];
    const float* q2      = (const float*)d_in[15];
    const float* k2      = (const float*)d_in[16];
    const float* v2      = (const float*)d_in[17];
    const float* o2_w    = (const float*)d_in[18];
    const float* o2_b    = (const float*)d_in[19];
    const float* ln3_w   = (const float*)d_in[20];
    const float* ln3_b   = (const float*)d_in[21];
    const float* ff1_w   = (const float*)d_in[22];
    const float* ff1_b   = (const float*)d_in[23];
    const float* ff2_w   = (const float*)d_in[24];
    const float* ff2_b   = (const float*)d_in[25];
    const float* pout_w  = (const float*)d_in[26];
    const float* pout_b  = (const float*)d_in[27];
    float* out = (float*)d_out;

    float *gnA, *res, *ln, *q, *k, *v, *attn, *ffh, *gg, *kc, *vc;
    cudaGetSymbolAddress((void**)&gnA,  g_gnA);
    cudaGetSymbolAddress((void**)&res,  g_res);
    cudaGetSymbolAddress((void**)&ln,   g_ln);
    cudaGetSymbolAddress((void**)&q,    g_q);
    cudaGetSymbolAddress((void**)&k,    g_k);
    cudaGetSymbolAddress((void**)&v,    g_v);
    cudaGetSymbolAddress((void**)&attn, g_attn);
    cudaGetSymbolAddress((void**)&ffh,  g_ffh);
    cudaGetSymbolAddress((void**)&gg,   g_gg);
    cudaGetSymbolAddress((void**)&kc,   g_kc);
    cudaGetSymbolAddress((void**)&vc,   g_vc);

    // 1. GroupNorm + transpose
    gn_stats_kernel<<<GROUPS, 256>>>(x);
    gn_apply_kernel<<<dim3(HW / 32, CCH / 32), dim3(32, 8)>>>(x, gn_w, gn_b, gnA);

    // 2. proj_in
    mgemm_kernel<true, false><<<ggrid(HW, CCH, 1), 256>>>(
        gnA, pin_w, pin_w, pin_w, pin_b, nullptr, res, res, res, HW, CCH, CCH);

    // 3. self-attention block
    ln_kernel<<<HW, CCH>>>(res, ln1_w, ln1_b, ln);
    mgemm_kernel<false, false><<<ggrid(HW, CCH, 3), 256>>>(
        ln, q1, k1, v1, nullptr, nullptr, q, k, v, HW, CCH, CCH);
    attn_kernel<<<dim3(HW / 64, HEADS), 128>>>(q, k, v, attn, HW);
    mgemm_kernel<false, false><<<ggrid(HW, CCH, 1), 256>>>(
        attn, o1_w, o1_w, o1_w, o1_b, res, res, res, res, HW, CCH, CCH);

    // 4. cross-attention block
    ln_kernel<<<HW, CCH>>>(res, ln2_w, ln2_b, ln);
    mgemm_kernel<false, false><<<ggrid(HW, CCH, 1), 256>>>(
        ln, q2, q2, q2, nullptr, nullptr, q, q, q, HW, CCH, CCH);
    mgemm_kernel<false, false><<<ggrid(CTXN, CCH, 2), 256>>>(
        context, k2, v2, v2, nullptr, nullptr, kc, vc, vc, CTXN, CCH, CTXD);
    attn_kernel<<<dim3(HW / 64, HEADS), 128>>>(q, kc, vc, attn, CTXN);
    mgemm_kernel<false, false><<<ggrid(HW, CCH, 1), 256>>>(
        attn, o2_w, o2_w, o2_w, o2_b, res, res, res, res, HW, CCH, CCH);

    // 5. GEGLU FF
    ln_kernel<<<HW, CCH>>>(res, ln3_w, ln3_b, ln);
    mgemm_kernel<false, false><<<ggrid(HW, 2 * FFI, 1), 256>>>(
        ln, ff1_w, ff1_w, ff1_w, ff1_b, nullptr, ffh, ffh, ffh, HW, 2 * FFI, CCH);
    geglu_kernel<<<(HW * FFI + 255) / 256, 256>>>(ffh, gg);
    mgemm_kernel<false, false><<<ggrid(HW, CCH, 1), 256>>>(
        gg, ff2_w, ff2_w, ff2_w, ff2_b, res, res, res, res, HW, CCH, FFI);

    // 6. proj_out + input residual
    mgemm_kernel<true, true><<<ggrid(CCH, HW, 1), 256>>>(
        pout_w, res, res, res, pout_b, x, out, out, out, CCH, HW, CCH);
}

// round 12
// speedup vs baseline: 2.9054x; 1.2979x over previous
#include <cuda_runtime.h>
#include <math.h>
#include <stdint.h>

// ---------------------------------------------------------------------------
// SpatialTransformer: bf16 m16n8k16 double-buffered GEMMs + tf32 mma attention.
// ---------------------------------------------------------------------------

#define HW    4096
#define CCH   320
#define GROUPS 32
#define CPG   10
#define HEADS 8
#define DH    40
#define CTXN  77
#define CTXD  768
#define FFI   1280

__device__ float g_mu[GROUPS], g_rs[GROUPS];
__device__ float g_gnA[HW * CCH];
__device__ float g_res[HW * CCH];
__device__ float g_ln[HW * CCH];
__device__ float g_q[HW * CCH];
__device__ float g_k[HW * CCH];
__device__ float g_v[HW * CCH];
__device__ float g_attn[HW * CCH];
__device__ float g_ffh[HW * 2 * FFI];
__device__ float g_gg[HW * FFI];
__device__ float g_kc[CTXN * CCH];
__device__ float g_vc[CTXN * CCH];

// ---------------------------------------------------------------------------
// GroupNorm stats
// ---------------------------------------------------------------------------
__global__ void gn_stats_kernel(const float* __restrict__ x) {
    int g = blockIdx.x;
    int tid = threadIdx.x;                 // 256
    const float* xg = x + (size_t)g * CPG * HW;
    float s = 0.f, s2 = 0.f;
    for (int i = tid; i < CPG * HW; i += 256) {
        float v = xg[i];
        s += v; s2 += v * v;
    }
    __shared__ float r1[8], r2[8];
    int lane = tid & 31, wp = tid >> 5;
    #pragma unroll
    for (int o = 16; o; o >>= 1) {
        s  += __shfl_xor_sync(0xffffffffu, s,  o);
        s2 += __shfl_xor_sync(0xffffffffu, s2, o);
    }
    if (lane == 0) { r1[wp] = s; r2[wp] = s2; }
    __syncthreads();
    if (tid == 0) {
        float t = 0.f, t2 = 0.f;
        for (int i = 0; i < 8; i++) { t += r1[i]; t2 += r2[i]; }
        float inv = 1.f / (float)(CPG * HW);
        float mean = t * inv;
        float var  = t2 * inv - mean * mean;
        g_mu[g] = mean;
        g_rs[g] = rsqrtf(var + 1e-6f);
    }
}

// ---------------------------------------------------------------------------
// GroupNorm apply + transpose
// ---------------------------------------------------------------------------
__global__ void gn_apply_kernel(const float* __restrict__ x, const float* __restrict__ w,
                                const float* __restrict__ b, float* __restrict__ o) {
    __shared__ float tile[32][33];
    int n0 = blockIdx.x * 32, c0 = blockIdx.y * 32;
    int tx = threadIdx.x, ty = threadIdx.y;  // 32 x 8
    for (int r = ty; r < 32; r += 8)
        tile[r][tx] = x[(size_t)(c0 + r) * HW + n0 + tx];
    __syncthreads();
    for (int r = ty; r < 32; r += 8) {
        int c = c0 + tx, n = n0 + r;
        int g = c / CPG;
        o[(size_t)n * CCH + c] = (tile[tx][r] - g_mu[g]) * g_rs[g] * w[c] + b[c];
    }
}

// ---------------------------------------------------------------------------
// precision helpers
// ---------------------------------------------------------------------------
__device__ __forceinline__ uint32_t f2tf(float f) {
    uint32_t u;
    asm("cvt.rna.tf32.f32 %0, %1;" : "=r"(u) : "f"(f));
    return u;
}

// pack: low half = lo (even k), high half = hi (odd k)
__device__ __forceinline__ uint32_t pack_bf16(float lo, float hi) {
    uint32_t r;
    asm("cvt.rn.bf16x2.f32 %0, %1, %2;" : "=r"(r) : "f"(hi), "f"(lo));
    return r;
}

__device__ __forceinline__ void mma_tf32(float c[4],
        uint32_t a0, uint32_t a1, uint32_t a2, uint32_t a3,
        uint32_t b0, uint32_t b1) {
    asm volatile(
        "mma.sync.aligned.m16n8k8.row.col.f32.tf32.tf32.f32 "
        "{%0,%1,%2,%3},{%4,%5,%6,%7},{%8,%9},{%0,%1,%2,%3};"
        : "+f"(c[0]), "+f"(c[1]), "+f"(c[2]), "+f"(c[3])
        : "r"(a0), "r"(a1), "r"(a2), "r"(a3), "r"(b0), "r"(b1));
}

__device__ __forceinline__ void mma_bf16(float c[4],
        uint32_t a0, uint32_t a1, uint32_t a2, uint32_t a3,
        uint32_t b0, uint32_t b1) {
    asm volatile(
        "mma.sync.aligned.m16n8k16.row.col.f32.bf16.bf16.f32 "
        "{%0,%1,%2,%3},{%4,%5,%6,%7},{%8,%9},{%0,%1,%2,%3};"
        : "+f"(c[0]), "+f"(c[1]), "+f"(c[2]), "+f"(c[3])
        : "r"(a0), "r"(a1), "r"(a2), "r"(a3), "r"(b0), "r"(b1));
}

// ---------------------------------------------------------------------------
// bf16 double-buffered tensor-core GEMM: C[M,N] = A[M,K] * B (+bias) (+resid)
//   TB=false: B is [K,N].  TB=true: B is [N,K].
// Tile 128x128, k-step 16 (packed bf16 pairs, 8 words/row), stride 9 words.
// Double-buffered smem: 1 barrier per k-step, global loads overlapped.
// Requires K % 16 == 0.
// ---------------------------------------------------------------------------
template <bool TB, bool BIAS_ROW>
__global__ __launch_bounds__(256) void mgemm_kernel(
        const float* __restrict__ A,
        const float* __restrict__ B0, const float* __restrict__ B1, const float* __restrict__ B2,
        const float* __restrict__ bias, const float* __restrict__ resid,
        float* __restrict__ C0, float* __restrict__ C1, float* __restrict__ C2,
        int M, int N, int K) {
    const float* B = (blockIdx.z == 0) ? B0 : (blockIdx.z == 1) ? B1 : B2;
    float*       C = (blockIdx.z == 0) ? C0 : (blockIdx.z == 1) ? C1 : C2;

    __shared__ uint32_t As[2][128 * 9];
    __shared__ uint32_t Bs[2][128 * 9];

    const int bm = blockIdx.y * 128, bn = blockIdx.x * 128;
    const int tid = threadIdx.x;
    const int lane = tid & 31;
    const int w = tid >> 5;
    const int m_off = (w >> 2) * 64;
    const int n_off = (w & 3) * 32;

    const int arow = tid >> 1;         // 0..127
    const int ab   = tid & 1;
    const int bkp  = tid >> 5;         // 0..7  (!TB)
    const int bnq  = (tid & 31) * 4;
    const int bnr  = tid >> 1;         // (TB)

    // staging registers (live across compute in DB loop)
    float4 av0, av1, bv0, bv1;

    auto load_tiles = [&](int k0) {
        {
            int gm = bm + arow;
            av0 = make_float4(0.f, 0.f, 0.f, 0.f);
            av1 = av0;
            if (gm < M) {
                const float* p = A + (size_t)gm * K + k0 + ab * 8;
                av0 = *(const float4*)(p);
                av1 = *(const float4*)(p + 4);
            }
        }
        if (!TB) {
            int gn = bn + bnq;
            const float* r0 = B + (size_t)(k0 + 2 * bkp) * N;
            const float* r1 = r0 + N;
            if (gn + 3 < N) {
                bv0 = *(const float4*)(r0 + gn);
                bv1 = *(const float4*)(r1 + gn);
            } else {
                bv0.x = (gn + 0 < N) ? r0[gn + 0] : 0.f;
                bv0.y = (gn + 1 < N) ? r0[gn + 1] : 0.f;
                bv0.z = (gn + 2 < N) ? r0[gn + 2] : 0.f;
                bv0.w = 0.f;
                bv1.x = (gn + 0 < N) ? r1[gn + 0] : 0.f;
                bv1.y = (gn + 1 < N) ? r1[gn + 1] : 0.f;
                bv1.z = (gn + 2 < N) ? r1[gn + 2] : 0.f;
                bv1.w = 0.f;
            }
        } else {
            int gn = bn + bnr;
            bv0 = make_float4(0.f, 0.f, 0.f, 0.f);
            bv1 = bv0;
            if (gn < N) {
                const float* p = B + (size_t)gn * K + k0 + ab * 8;
                bv0 = *(const float4*)(p);
                bv1 = *(const float4*)(p + 4);
            }
        }
    };

    auto store_tiles = [&](int buf) {
        {
            uint32_t* dst = &As[buf][arow * 9 + ab * 4];
            dst[0] = pack_bf16(av0.x, av0.y);
            dst[1] = pack_bf16(av0.z, av0.w);
            dst[2] = pack_bf16(av1.x, av1.y);
            dst[3] = pack_bf16(av1.z, av1.w);
        }
        if (!TB) {
            Bs[buf][(bnq + 0) * 9 + bkp] = pack_bf16(bv0.x, bv1.x);
            Bs[buf][(bnq + 1) * 9 + bkp] = pack_bf16(bv0.y, bv1.y);
            Bs[buf][(bnq + 2) * 9 + bkp] = pack_bf16(bv0.z, bv1.z);
            Bs[buf][(bnq + 3) * 9 + bkp] = pack_bf16(bv0.w, bv1.w);
        } else {
            uint32_t* dst = &Bs[buf][bnr * 9 + ab * 4];
            dst[0] = pack_bf16(bv0.x, bv0.y);
            dst[1] = pack_bf16(bv0.z, bv0.w);
            dst[2] = pack_bf16(bv1.x, bv1.y);
            dst[3] = pack_bf16(bv1.z, bv1.w);
        }
    };

    float acc[4][4][4];
    #pragma unroll
    for (int i = 0; i < 4; i++)
        #pragma unroll
        for (int j = 0; j < 4; j++)
            #pragma unroll
            for (int r = 0; r < 4; r++) acc[i][j][r] = 0.f;

    const int nsteps = K / 16;
    load_tiles(0);
    store_tiles(0);
    __syncthreads();

    const int fq = lane >> 2;
    const int fr = lane & 3;

    for (int s = 0; s < nsteps; s++) {
        const int buf = s & 1;
        if (s + 1 < nsteps) load_tiles((s + 1) * 16);

        uint32_t af[4][4], bf[4][2];
        #pragma unroll
        for (int mt = 0; mt < 4; mt++) {
            int row = m_off + mt * 16 + fq;
            af[mt][0] = As[buf][row * 9 + fr];
            af[mt][1] = As[buf][(row + 8) * 9 + fr];
            af[mt][2] = As[buf][row * 9 + fr + 4];
            af[mt][3] = As[buf][(row + 8) * 9 + fr + 4];
        }
        #pragma unroll
        for (int nt = 0; nt < 4; nt++) {
            int col = n_off + nt * 8 + fq;
            bf[nt][0] = Bs[buf][col * 9 + fr];
            bf[nt][1] = Bs[buf][col * 9 + fr + 4];
        }
        #pragma unroll
        for (int mt = 0; mt < 4; mt++)
            #pragma unroll
            for (int nt = 0; nt < 4; nt++)
                mma_bf16(acc[mt][nt], af[mt][0], af[mt][1], af[mt][2], af[mt][3],
                         bf[nt][0], bf[nt][1]);

        if (s + 1 < nsteps) store_tiles(buf ^ 1);
        __syncthreads();
    }

    #pragma unroll
    for (int mt = 0; mt < 4; mt++) {
        #pragma unroll
        for (int nt = 0; nt < 4; nt++) {
            #pragma unroll
            for (int r = 0; r < 4; r++) {
                int gm = bm + m_off + mt * 16 + fq + (r >= 2 ? 8 : 0);
                int gn = bn + n_off + nt * 8 + 2 * fr + (r & 1);
                if (gm >= M || gn >= N) continue;
                float v = acc[mt][nt][r];
                if (bias)  v += BIAS_ROW ? bias[gm] : bias[gn];
                if (resid) v += resid[(size_t)gm * N + gn];
                C[(size_t)gm * N + gn] = v;
            }
        }
    }
}

// ---------------------------------------------------------------------------
// LayerNorm over last dim 320
// ---------------------------------------------------------------------------
__global__ void ln_kernel(const float* __restrict__ x, const float* __restrict__ w,
                          const float* __restrict__ b, float* __restrict__ y) {
    int row = blockIdx.x;
    int tid = threadIdx.x;                 // 320
    float v = x[(size_t)row * CCH + tid];
    __shared__ float red[10];
    __shared__ float s_mean, s_rstd;
    int lane = tid & 31, wp = tid >> 5;
    float s = v;
    #pragma unroll
    for (int o = 16; o; o >>= 1) s += __shfl_xor_sync(0xffffffffu, s, o);
    if (lane == 0) red[wp] = s;
    __syncthreads();
    if (tid == 0) {
        float t = 0.f;
        for (int i = 0; i < 10; i++) t += red[i];
        s_mean = t / (float)CCH;
    }
    __syncthreads();
    float d = v - s_mean;
    s = d * d;
    #pragma unroll
    for (int o = 16; o; o >>= 1) s += __shfl_xor_sync(0xffffffffu, s, o);
    if (lane == 0) red[wp] = s;
    __syncthreads();
    if (tid == 0) {
        float t = 0.f;
        for (int i = 0; i < 10; i++) t += red[i];
        s_rstd = rsqrtf(t / (float)CCH + 1e-5f);
    }
    __syncthreads();
    y[(size_t)row * CCH + tid] = d * s_rstd * w[tid] + b[tid];
}

// ---------------------------------------------------------------------------
// tf32 mma flash attention (proven R7). 128 threads, 64 queries x 1 head.
// ---------------------------------------------------------------------------
#define SK 44
#define SP 68

__global__ __launch_bounds__(128) void attn_kernel(
    const float* __restrict__ Q, const float* __restrict__ K,
    const float* __restrict__ V, float* __restrict__ O, int Mk) {
    __shared__ uint32_t Ks[64 * SK];
    __shared__ uint32_t Vs[64 * SK];
    __shared__ float P[64 * SP];
    __shared__ float s_m[64], s_l[64], s_al[64];

    const int tid = threadIdx.x;
    const int lane = tid & 31;
    const int w = tid >> 5;
    const int m_off = w * 16;
    const int fq = lane >> 2;
    const int fr = lane & 3;
    const int h = blockIdx.y;
    const int q0 = blockIdx.x * 64;
    const int off = h * DH;
    const float scale = 0.15811388300841898f;  // 40^-0.5

    uint32_t qf[5][4];
    {
        const float* Qr0 = Q + (size_t)(q0 + m_off + fq) * CCH + off;
        const float* Qr1 = Qr0 + 8 * CCH;
        #pragma unroll
        for (int ks = 0; ks < 5; ks++) {
            qf[ks][0] = f2tf(Qr0[ks * 8 + fr] * scale);
            qf[ks][1] = f2tf(Qr1[ks * 8 + fr] * scale);
            qf[ks][2] = f2tf(Qr0[ks * 8 + fr + 4] * scale);
            qf[ks][3] = f2tf(Qr1[ks * 8 + fr + 4] * scale);
        }
    }
    if (tid < 64) { s_m[tid] = -INFINITY; s_l[tid] = 0.f; }

    float acc_o[5][4];
    #pragma unroll
    for (int nt = 0; nt < 5; nt++)
        #pragma unroll
        for (int r = 0; r < 4; r++) acc_o[nt][r] = 0.f;

    for (int kb = 0; kb < Mk; kb += 64) {
        const int nk = min(64, Mk - kb);
        for (int i = tid; i < 640; i += 128) {
            int r = i / 10, cq = (i % 10) * 4;
            float4 kv = make_float4(0.f, 0.f, 0.f, 0.f);
            float4 vv = make_float4(0.f, 0.f, 0.f, 0.f);
            if (r < nk) {
                kv = *(const float4*)(K + (size_t)(kb + r) * CCH + off + cq);
                vv = *(const float4*)(V + (size_t)(kb + r) * CCH + off + cq);
            }
            Ks[r * SK + cq + 0] = f2tf(kv.x);
            Ks[r * SK + cq + 1] = f2tf(kv.y);
            Ks[r * SK + cq + 2] = f2tf(kv.z);
            Ks[r * SK + cq + 3] = f2tf(kv.w);
            Vs[r * SK + cq + 0] = f2tf(vv.x);
            Vs[r * SK + cq + 1] = f2tf(vv.y);
            Vs[r * SK + cq + 2] = f2tf(vv.z);
            Vs[r * SK + cq + 3] = f2tf(vv.w);
        }
        __syncthreads();

        float s[8][4];
        #pragma unroll
        for (int nt = 0; nt < 8; nt++)
            #pragma unroll
            for (int r = 0; r < 4; r++) s[nt][r] = 0.f;
        #pragma unroll
        for (int ks = 0; ks < 5; ks++) {
            #pragma unroll
            for (int nt = 0; nt < 8; nt++) {
                uint32_t b0 = Ks[(nt * 8 + fq) * SK + ks * 8 + fr];
                uint32_t b1 = Ks[(nt * 8 + fq) * SK + ks * 8 + fr + 4];
                mma_tf32(s[nt], qf[ks][0], qf[ks][1], qf[ks][2], qf[ks][3], b0, b1);
            }
        }
        {
            int row0 = (m_off + fq) * SP, row1 = row0 + 8 * SP;
            #pragma unroll
            for (int nt = 0; nt < 8; nt++) {
                int gn = nt * 8 + 2 * fr;
                P[row0 + gn]     = (gn     < nk) ? s[nt][0] : -INFINITY;
                P[row0 + gn + 1] = (gn + 1 < nk) ? s[nt][1] : -INFINITY;
                P[row1 + gn]     = (gn     < nk) ? s[nt][2] : -INFINITY;
                P[row1 + gn + 1] = (gn + 1 < nk) ? s[nt][3] : -INFINITY;
            }
        }
        __syncthreads();

        {
            int r = tid >> 1, hh = tid & 1;
            int base = r * SP + hh * 32;
            float mx = -INFINITY;
            #pragma unroll
            for (int j = 0; j < 32; j++) mx = fmaxf(mx, P[base + j]);
            mx = fmaxf(mx, __shfl_xor_sync(0xffffffffu, mx, 1));
            float mold = s_m[r];
            float mnew = fmaxf(mold, mx);
            float sum = 0.f;
            #pragma unroll
            for (int j = 0; j < 32; j++) {
                float p = __expf(P[base + j] - mnew);
                P[base + j] = p;
                sum += p;
            }
            sum += __shfl_xor_sync(0xffffffffu, sum, 1);
            if (hh == 0) {
                float al = __expf(mold - mnew);
                s_l[r] = s_l[r] * al + sum;
                s_m[r] = mnew;
                s_al[r] = al;
            }
        }
        __syncthreads();

        {
            float al0 = s_al[m_off + fq], al1 = s_al[m_off + fq + 8];
            #pragma unroll
            for (int nt = 0; nt < 5; nt++) {
                acc_o[nt][0] *= al0; acc_o[nt][1] *= al0;
                acc_o[nt][2] *= al1; acc_o[nt][3] *= al1;
            }
            int row0 = (m_off + fq) * SP, row1 = row0 + 8 * SP;
            #pragma unroll
            for (int kt = 0; kt < 8; kt++) {
                uint32_t pa0 = f2tf(P[row0 + kt * 8 + fr]);
                uint32_t pa1 = f2tf(P[row1 + kt * 8 + fr]);
                uint32_t pa2 = f2tf(P[row0 + kt * 8 + fr + 4]);
                uint32_t pa3 = f2tf(P[row1 + kt * 8 + fr + 4]);
                #pragma unroll
                for (int nt = 0; nt < 5; nt++) {
                    uint32_t b0 = Vs[(kt * 8 + fr) * SK + nt * 8 + fq];
                    uint32_t b1 = Vs[(kt * 8 + fr + 4) * SK + nt * 8 + fq];
                    mma_tf32(acc_o[nt], pa0, pa1, pa2, pa3, b0, b1);
                }
            }
        }
        __syncthreads();
    }

    {
        float inv0 = 1.f / s_l[m_off + fq];
        float inv1 = 1.f / s_l[m_off + fq + 8];
        size_t gm0 = (size_t)(q0 + m_off + fq) * CCH + off;
        size_t gm1 = gm0 + 8 * CCH;
        #pragma unroll
        for (int nt = 0; nt < 5; nt++) {
            int gn = nt * 8 + 2 * fr;
            O[gm0 + gn]     = acc_o[nt][0] * inv0;
            O[gm0 + gn + 1] = acc_o[nt][1] * inv0;
            O[gm1 + gn]     = acc_o[nt][2] * inv1;
            O[gm1 + gn + 1] = acc_o[nt][3] * inv1;
        }
    }
}

// ---------------------------------------------------------------------------
// GEGLU
// ---------------------------------------------------------------------------
__global__ void geglu_kernel(const float* __restrict__ h, float* __restrict__ o) {
    int idx = blockIdx.x * blockDim.x + threadIdx.x;
    if (idx >= HW * FFI) return;
    int n = idx / FFI, j = idx % FFI;
    float a = h[(size_t)n * 2 * FFI + j];
    float g = h[(size_t)n * 2 * FFI + FFI + j];
    float ge = 0.5f * g * (1.f + erff(g * 0.70710678118654752f));
    o[idx] = a * ge;
}

// ---------------------------------------------------------------------------
// Host launcher
// ---------------------------------------------------------------------------
static inline dim3 ggrid(int M, int N, int Z) {
    return dim3((N + 127) / 128, (M + 127) / 128, Z);
}

extern "C" void kernel_launch(void* const* d_in, const int* in_sizes, int n_in,
                              void* d_out, int out_size) {
    const float* x       = (const float*)d_in[0];
    const float* context = (const float*)d_in[1];
    const float* gn_w    = (const float*)d_in[2];
    const float* gn_b    = (const float*)d_in[3];
    const float* pin_w   = (const float*)d_in[4];
    const float* pin_b   = (const float*)d_in[5];
    const float* ln1_w   = (const float*)d_in[6];
    const float* ln1_b   = (const float*)d_in[7];
    const float* q1      = (const float*)d_in[8];
    const float* k1      = (const float*)d_in[9];
    const float* v1      = (const float*)d_in[10];
    const float* o1_w    = (const float*)d_in[11];
    const float* o1_b    = (const float*)d_in[12];
    const float* ln2_w   = (const float*)d_in[13];
    const float* ln2_b   = (const float*)d_in[14];
    const float* q2      = (const float*)d_in[15];
    const float* k2      = (const float*)d_in[16];
    const float* v2      = (const float*)d_in[17];
    const float* o2_w    = (const float*)d_in[18];
    const float* o2_b    = (const float*)d_in[19];
    const float* ln3_w   = (const float*)d_in[20];
    const float* ln3_b   = (const float*)d_in[21];
    const float* ff1_w   = (const float*)d_in[22];
    const float* ff1_b   = (const float*)d_in[23];
    const float* ff2_w   = (const float*)d_in[24];
    const float* ff2_b   = (const float*)d_in[25];
    const float* pout_w  = (const float*)d_in[26];
    const float* pout_b  = (const float*)d_in[27];
    float* out = (float*)d_out;

    float *gnA, *res, *ln, *q, *k, *v, *attn, *ffh, *gg, *kc, *vc;
    cudaGetSymbolAddress((void**)&gnA,  g_gnA);
    cudaGetSymbolAddress((void**)&res,  g_res);
    cudaGetSymbolAddress((void**)&ln,   g_ln);
    cudaGetSymbolAddress((void**)&q,    g_q);
    cudaGetSymbolAddress((void**)&k,    g_k);
    cudaGetSymbolAddress((void**)&v,    g_v);
    cudaGetSymbolAddress((void**)&attn, g_attn);
    cudaGetSymbolAddress((void**)&ffh,  g_ffh);
    cudaGetSymbolAddress((void**)&gg,   g_gg);
    cudaGetSymbolAddress((void**)&kc,   g_kc);
    cudaGetSymbolAddress((void**)&vc,   g_vc);

    // 1. GroupNorm + transpose
    gn_stats_kernel<<<GROUPS, 256>>>(x);
    gn_apply_kernel<<<dim3(HW / 32, CCH / 32), dim3(32, 8)>>>(x, gn_w, gn_b, gnA);

    // 2. proj_in
    mgemm_kernel<true, false><<<ggrid(HW, CCH, 1), 256>>>(
        gnA, pin_w, pin_w, pin_w, pin_b, nullptr, res, res, res, HW, CCH, CCH);

    // 3. self-attention block
    ln_kernel<<<HW, CCH>>>(res, ln1_w, ln1_b, ln);
    mgemm_kernel<false, false><<<ggrid(HW, CCH, 3), 256>>>(
        ln, q1, k1, v1, nullptr, nullptr, q, k, v, HW, CCH, CCH);
    attn_kernel<<<dim3(HW / 64, HEADS), 128>>>(q, k, v, attn, HW);
    mgemm_kernel<false, false><<<ggrid(HW, CCH, 1), 256>>>(
        attn, o1_w, o1_w, o1_w, o1_b, res, res, res, res, HW, CCH, CCH);

    // 4. cross-attention block
    ln_kernel<<<HW, CCH>>>(res, ln2_w, ln2_b, ln);
    mgemm_kernel<false, false><<<ggrid(HW, CCH, 1), 256>>>(
        ln, q2, q2, q2, nullptr, nullptr, q, q, q, HW, CCH, CCH);
    mgemm_kernel<false, false><<<ggrid(CTXN, CCH, 2), 256>>>(
        context, k2, v2, v2, nullptr, nullptr, kc, vc, vc, CTXN, CCH, CTXD);
    attn_kernel<<<dim3(HW / 64, HEADS), 128>>>(q, kc, vc, attn, CTXN);
    mgemm_kernel<false, false><<<ggrid(HW, CCH, 1), 256>>>(
        attn, o2_w, o2_w, o2_w, o2_b, res, res, res, res, HW, CCH, CCH);

    // 5. GEGLU FF
    ln_kernel<<<HW, CCH>>>(res, ln3_w, ln3_b, ln);
    mgemm_kernel<false, false><<<ggrid(HW, 2 * FFI, 1), 256>>>(
        ln, ff1_w, ff1_w, ff1_w, ff1_b, nullptr, ffh, ffh, ffh, HW, 2 * FFI, CCH);
    geglu_kernel<<<(HW * FFI + 255) / 256, 256>>>(ffh, gg);
    mgemm_kernel<false, false><<<ggrid(HW, CCH, 1), 256>>>(
        gg, ff2_w, ff2_w, ff2_w, ff2_b, res, res, res, res, HW, CCH, FFI);

    // 6. proj_out + input residual
    mgemm_kernel<true, true><<<ggrid(CCH, HW, 1), 256>>>(
        pout_w, res, res, res, pout_b, x, out, out, out, CCH, HW, CCH);
}